// round 17
// baseline (speedup 1.0000x reference)
#include <cuda_runtime.h>
#include <math.h>

#define HIDDEN  128
#define NCLASS  4
#define BB      256
#define TT      512
#define BTOK    8                 // tokens per batch
#define NBATCH  (TT / BTOK)       // 64 batches

// ---------------------------------------------------------------- helpers
__device__ __forceinline__ unsigned smem_u32(const void* p) {
    return (unsigned)__cvta_generic_to_shared(p);
}
__device__ __forceinline__ void cp_async16(void* dst, const void* src) {
    asm volatile("cp.async.cg.shared.global [%0], [%1], 16;"
                 :: "r"(smem_u32(dst)), "l"(src));
}
__device__ __forceinline__ void cp_commit() {
    asm volatile("cp.async.commit_group;");
}
__device__ __forceinline__ void cp_wait1() {
    asm volatile("cp.async.wait_group 1;");
}
__device__ __forceinline__ void cp_wait0() {
    asm volatile("cp.async.wait_group 0;");
}
#define BAR_SYNC(id, cnt) \
    asm volatile("bar.sync %0, %1;" :: "r"(id), "r"(cnt) : "memory")
#define BAR_ARRIVE(id, cnt) \
    asm volatile("bar.arrive %0, %1;" :: "r"(id), "r"(cnt) : "memory")

__device__ __forceinline__ unsigned long long
fma2(unsigned long long a, unsigned long long b, unsigned long long c) {
    unsigned long long d;
    asm("fma.rn.f32x2 %0, %1, %2, %3;" : "=l"(d) : "l"(a), "l"(b), "l"(c));
    return d;
}
__device__ __forceinline__ unsigned long long
add2(unsigned long long a, unsigned long long b) {
    unsigned long long d;
    asm("add.rn.f32x2 %0, %1, %2;" : "=l"(d) : "l"(a), "l"(b));
    return d;
}
__device__ __forceinline__ float2 unpack2(unsigned long long v) {
    float2 r;
    asm("mov.b64 {%0, %1}, %2;" : "=f"(r.x), "=f"(r.y) : "l"(v));
    return r;
}
__device__ __forceinline__ unsigned long long pack2(float a, float b) {
    unsigned long long r;
    asm("mov.b64 %0, {%1, %2};" : "=l"(r) : "f"(a), "f"(b));
    return r;
}
__device__ __forceinline__ unsigned long long
shfl64_xor(unsigned long long v, int m) {
    unsigned lo, hi;
    asm("mov.b64 {%0, %1}, %2;" : "=r"(lo), "=r"(hi) : "l"(v));
    lo = __shfl_xor_sync(0xffffffffu, lo, m);
    hi = __shfl_xor_sync(0xffffffffu, hi, m);
    unsigned long long r;
    asm("mov.b64 %0, {%1, %2};" : "=l"(r) : "r"(lo), "r"(hi));
    return r;
}

// Clamp-free tanh: tanh(x) = 1 - 2/(e^{2x}+1) = 1 - 2/(2^{2x*log2e}+1).
// ex2 overflow -> inf -> rcp 0 -> +1; underflow -> 0 -> rcp(1) -> -1. Exact
// saturation at extremes, no clamps needed.
__device__ __forceinline__ float fast_tanh2(float x) {
    float t = x * 2.8853900817779268f;     // 2 * log2(e)
    float e;
    asm("ex2.approx.f32 %0, %1;" : "=f"(e) : "f"(t));
    float r;
    asm("rcp.approx.f32 %0, %1;" : "=f"(r) : "f"(e + 1.0f));
    return fmaf(-2.0f, r, 1.0f);
}

// interleaved float offset within a 128-float row:
//   k -> ((k&31)>>2)*16 + (k>>5)*4 + (k&3)
__device__ __forceinline__ int ilv_off(int k) {
    return ((k & 31) >> 2) * 16 + (k >> 5) * 4 + (k & 3);
}

// Per-thread quarter dot for 4 outputs. src = (u2*)row_base + q.
__device__ __forceinline__ void dot4q(
    const ulonglong2* __restrict__ src,
    const unsigned long long (* __restrict__ wq)[16],
    float* __restrict__ s)
{
    ulonglong2 A[8];
    #pragma unroll
    for (int c = 0; c < 8; ++c) A[c] = src[c * 4];
    #pragma unroll
    for (int j = 0; j < 4; ++j) {
        unsigned long long a = 0, b = 0;
        #pragma unroll
        for (int c = 0; c < 8; ++c) {
            a = fma2(wq[j][2 * c],     A[c].x, a);
            b = fma2(wq[j][2 * c + 1], A[c].y, b);
        }
        float2 u = unpack2(add2(a, b));
        s[j] = u.x + u.y;
    }
}

// Cross-quarter reduce of 4 scalars (packed butterfly over lane bits 3,4).
__device__ __forceinline__ float qreduce4(const float* __restrict__ s, int q) {
    unsigned long long P01 = pack2(s[0], s[1]);
    unsigned long long P23 = pack2(s[2], s[3]);
    P01 = add2(P01, shfl64_xor(P01, 8));
    P01 = add2(P01, shfl64_xor(P01, 16));
    P23 = add2(P23, shfl64_xor(P23, 8));
    P23 = add2(P23, shfl64_xor(P23, 16));
    float2 u01 = unpack2(P01), u23 = unpack2(P23);
    return (q < 2) ? (q == 0 ? u01.x : u01.y)
                   : (q == 2 ? u23.x : u23.y);
}

// ---------------------------------------------------------------------------
// Shared layout (float offsets). emb and h INTERLEAVED; xp/mlp normal.
//   ids  [2 rows][512]  (ints)                        1024
//   emb  [2 bufs][8 tok][2 rows][128]                 4096
//   xp   [2 bufs][8 tok][2 rows][128]                 4096
//   h    [2 bufs][2 rows][128]                         512
//   mlp  [2 rows][256]                                 512
//   stg  weight staging / final-h scratch             4096
// ---------------------------------------------------------------------------
#define SH_IDS  0
#define SH_EMB  1024
#define SH_XP   (1024 + 4096)
#define SH_H    (1024 + 4096 + 4096)
#define SH_MLP  (SH_H + 512)
#define SH_STG  (SH_MLP + 512)
#define SH_TOT  (SH_STG + 4096)      // 14336 floats = 56KB

// Barrier ids: 0 __syncthreads(256); 1 consumer h-publish (128);
//   3 producer emb-visibility (128); 4+buf full[buf] (256); 6+buf empty (256)

__global__ void __launch_bounds__(256, 1) fused_kernel(
    const int* __restrict__ x, const float* __restrict__ emb,
    const float* __restrict__ W_ih, const float* __restrict__ W_hh,
    const float* __restrict__ b_ih, const float* __restrict__ b_hh,
    const float* __restrict__ h0,
    const float* __restrict__ W1, const float* __restrict__ b1,
    const float* __restrict__ W2, const float* __restrict__ b2,
    float* __restrict__ logits, float* __restrict__ out_hidden)
{
    extern __shared__ float sh[];
    int*   s_ids = (int*)(sh + SH_IDS);
    float* s_emb = sh + SH_EMB;
    float* s_xp  = sh + SH_XP;
    float* s_h   = sh + SH_H;
    float* s_mlp = sh + SH_MLP;
    float* s_stg = sh + SH_STG;

    const int tid  = threadIdx.x;
    const int lane = tid & 31;
    const int w    = tid >> 5;              // 0..7
    const int b0   = blockIdx.x * 2;
    const bool is_prod = (w >= 4);
    const int q    = lane >> 3;             // K-quarter
    const int oid  = lane & 7;
    const int obase = (is_prod ? (w - 4) : w) * 32;
    const int out  = obase + oid * 4 + q;   // this lane's finalize output
    const int ilv  = ilv_off(out);

    // ---- stage token ids for both rows
    for (int i = tid; i < 2 * TT; i += 256) {
        int row = i >> 9, t = i & 511;
        s_ids[i] = x[(size_t)(b0 + row) * TT + t];
    }

    // ---- load weight slices: wq[j][c] = W[obase+oid*4+j][q*32 .. +32)
    unsigned long long wq[4][16];
    for (int p = 0; p < 4; ++p) {
        for (int i = tid; i < 4096; i += 256)
            s_stg[i] = W_hh[p * 4096 + i];
        __syncthreads();
        if (!is_prod && (obase >> 5) == p) {
            #pragma unroll
            for (int j = 0; j < 4; ++j) {
                const unsigned long long* r = (const unsigned long long*)
                    (s_stg + (oid * 4 + j) * 128);
                #pragma unroll
                for (int c = 0; c < 16; ++c) wq[j][c] = r[q * 16 + c];
            }
        }
        __syncthreads();
    }
    for (int p = 0; p < 4; ++p) {
        for (int i = tid; i < 4096; i += 256)
            s_stg[i] = W_ih[p * 4096 + i];
        __syncthreads();
        if (is_prod && (obase >> 5) == p) {
            #pragma unroll
            for (int j = 0; j < 4; ++j) {
                const unsigned long long* r = (const unsigned long long*)
                    (s_stg + (oid * 4 + j) * 128);
                #pragma unroll
                for (int c = 0; c < 16; ++c) wq[j][c] = r[q * 16 + c];
            }
        }
        __syncthreads();
    }
    const float bias = b_ih[out] + b_hh[out];

    // ---- init h buffer 0 (interleaved), by consumer threads
    if (!is_prod) {
        s_h[ilv_off(tid & 127)]       = h0[(size_t)b0 * HIDDEN + (tid & 127)];
        s_h[128 + ilv_off(tid & 127)] = h0[(size_t)(b0 + 1) * HIDDEN + (tid & 127)];
    }
    __syncthreads();

    if (is_prod) {
        // ============ PRODUCER: xp for all 16 (token,row) pairs per batch.
        const int p = tid - 128;      // 0..127

        // prologue: stage emb batch 0 into buf 0 (interleaved; 4 passes)
        #pragma unroll
        for (int cc = 0; cc < 4; ++cc) {
            int c = p + cc * 128;                // 0..511
            int j = c >> 6, row = (c >> 5) & 1, part = c & 31;
            int id = s_ids[row * TT + 0 + j];
            cp_async16(s_emb + j * 256 + row * 128
                           + (part & 7) * 16 + (part >> 3) * 4,
                       emb + (size_t)id * HIDDEN + part * 4);
        }
        cp_commit();

        for (int bb = 0; bb < NBATCH; ++bb) {
            const int buf = bb & 1;
            if (bb >= 2) BAR_SYNC(6 + buf, 256);         // xp slot empty

            if (bb + 1 < NBATCH) {                       // stage batch bb+1
                const int nb = buf ^ 1, T = BTOK * (bb + 1);
                #pragma unroll
                for (int cc = 0; cc < 4; ++cc) {
                    int c = p + cc * 128;
                    int j = c >> 6, row = (c >> 5) & 1, part = c & 31;
                    int id = s_ids[row * TT + T + j];
                    cp_async16(s_emb + nb * 2048 + j * 256 + row * 128
                                   + (part & 7) * 16 + (part >> 3) * 4,
                               emb + (size_t)id * HIDDEN + part * 4);
                }
                cp_commit();
                cp_wait1();
            } else {
                cp_wait0();
            }
            BAR_SYNC(3, 128);                            // emb bb visible

            #pragma unroll
            for (int j = 0; j < BTOK; ++j) {
                #pragma unroll
                for (int r = 0; r < 2; ++r) {
                    const ulonglong2* e = (const ulonglong2*)
                        (s_emb + buf * 2048 + j * 256 + r * 128) + q;
                    float s[4];
                    dot4q(e, wq, s);
                    float v = qreduce4(s, q);
                    s_xp[buf * 2048 + j * 256 + r * 128 + out] = v + bias;
                }
            }
            BAR_ARRIVE(4 + buf, 256);                    // xp slot full
        }
    } else {
        // ============ CONSUMER: dual-row recurrence, quarter-split.
        float hc0 = 0.f, hc1 = 0.f;

        for (int bb = 0; bb < NBATCH; ++bb) {
            const int buf = bb & 1;
            BAR_SYNC(4 + buf, 256);                      // xp batch full

            float xv0[BTOK], xv1[BTOK];
            #pragma unroll
            for (int j = 0; j < BTOK; ++j) {
                xv0[j] = s_xp[buf * 2048 + j * 256 + out];
                xv1[j] = s_xp[buf * 2048 + j * 256 + 128 + out];
            }
            BAR_ARRIVE(6 + buf, 256);    // EARLY release: xp copied to regs

            #pragma unroll
            for (int j = 0; j < BTOK; ++j) {
                const ulonglong2* h0v = (const ulonglong2*)
                    (s_h + (j & 1) * 256) + q;
                const ulonglong2* h1v = (const ulonglong2*)
                    (s_h + (j & 1) * 256 + 128) + q;

                float s0[4], s1[4];
                dot4q(h0v, wq, s0);
                dot4q(h1v, wq, s1);
                float v0 = qreduce4(s0, q);
                float v1 = qreduce4(s1, q);

                hc0 = fast_tanh2(v0 + xv0[j]);
                hc1 = fast_tanh2(v1 + xv1[j]);
                float* hn = s_h + ((j + 1) & 1) * 256;
                hn[ilv]       = hc0;
                hn[128 + ilv] = hc1;
                BAR_SYNC(1, 128);                        // publish h
            }
        }
        out_hidden[(size_t)b0 * HIDDEN + out]       = hc0;
        out_hidden[(size_t)(b0 + 1) * HIDDEN + out] = hc1;
        // final h, normal layout, for the head
        s_stg[out]       = hc0;
        s_stg[128 + out] = hc1;
    }

    // ============ fused MLP head (final h in s_stg, normal layout)
    __syncthreads();
    {
        const int m = tid;               // 0..255: one W1 row, both batch rows
        const float4* w4 = (const float4*)(W1 + (size_t)m * HIDDEN);
        float acc0 = b1[m], acc1 = acc0;
        const float4* h40 = (const float4*)(s_stg);
        const float4* h41 = (const float4*)(s_stg + 128);
        #pragma unroll 8
        for (int k4 = 0; k4 < 32; ++k4) {
            float4 ww = __ldg(&w4[k4]);
            float4 u = h40[k4];
            float4 v = h41[k4];
            acc0 = fmaf(ww.x, u.x, acc0); acc0 = fmaf(ww.y, u.y, acc0);
            acc0 = fmaf(ww.z, u.z, acc0); acc0 = fmaf(ww.w, u.w, acc0);
            acc1 = fmaf(ww.x, v.x, acc1); acc1 = fmaf(ww.y, v.y, acc1);
            acc1 = fmaf(ww.z, v.z, acc1); acc1 = fmaf(ww.w, v.w, acc1);
        }
        s_mlp[m]       = fmaxf(acc0, 0.0f);
        s_mlp[256 + m] = fmaxf(acc1, 0.0f);
    }
    __syncthreads();

    if (tid < 8) {
        const int r = tid >> 2, cls = tid & 3;
        const float* mv = s_mlp + r * 256;
        const float* w2 = W2 + (size_t)cls * (2 * HIDDEN);
        float acc = b2[cls];
        #pragma unroll 8
        for (int k = 0; k < 256; ++k)
            acc = fmaf(mv[k], __ldg(&w2[k]), acc);
        logits[(size_t)(b0 + r) * NCLASS + cls] = acc;
    }
}

// ---------------------------------------------------------------------------
extern "C" void kernel_launch(void* const* d_in, const int* in_sizes, int n_in,
                              void* d_out, int out_size)
{
    const int*   x    = (const int*)  d_in[0];
    const float* h0   = (const float*)d_in[1];
    const float* emb  = (const float*)d_in[2];
    const float* W_ih = (const float*)d_in[3];
    const float* W_hh = (const float*)d_in[4];
    const float* b_ih = (const float*)d_in[5];
    const float* b_hh = (const float*)d_in[6];
    const float* W1   = (const float*)d_in[7];
    const float* b1   = (const float*)d_in[8];
    const float* W2   = (const float*)d_in[9];
    const float* b2   = (const float*)d_in[10];

    float* out    = (float*)d_out;
    float* logits = out;                 // [256*4]
    float* hidden = out + BB * NCLASS;   // [256*128]

    const int smem = SH_TOT * sizeof(float);   // 56KB
    cudaFuncSetAttribute(fused_kernel,
                         cudaFuncAttributeMaxDynamicSharedMemorySize, smem);

    fused_kernel<<<BB / 2, 256, smem>>>(x, emb, W_ih, W_hh, b_ih, b_hh, h0,
                                        W1, b1, W2, b2, logits, hidden);
}